// round 1
// baseline (speedup 1.0000x reference)
#include <cuda_runtime.h>
#include <cuda_bf16.h>
#include <cstdint>

#define N_TOK 8192
#define C_CH  64
#define CR_   32

// Scratch (static __device__ allocation is the sanctioned scratch mechanism)
__device__ unsigned g_qT[N_TOK * 16];              // [8192][32] bf16, scaled by 32^-0.25
__device__ unsigned g_E[(size_t)N_TOK * 4096];     // [8192][8192] bf16 = exp(S)
__device__ float    g_Z[N_TOK];                    // row sums of exp(S)
__device__ unsigned g_vp[C_CH * 4096];             // [64][8192] bf16 = x / Z[n]
__device__ __align__(16) float g_P[8 * C_CH * N_TOK]; // split-K partials (16MB)

// ---------------- helpers ----------------

// fast exp: exp(x) = 2^(x*log2e), magic-number rounding + deg-5 poly, FMA-pipe only
static __device__ __forceinline__ float fexp(float x) {
    float y = x * 1.44269504088896341f;
    float r = y + 12582912.0f;                       // round-to-nearest via magic
    int   i = __float_as_int(r) - 0x4B400000;        // integer part
    float f = y - (r - 12582912.0f);                 // frac in [-0.5, 0.5]
    float p =               1.3333558146428443e-3f;
    p = fmaf(p, f, 9.618129842071803e-3f);
    p = fmaf(p, f, 5.550410866482158e-2f);
    p = fmaf(p, f, 2.402265069591007e-1f);
    p = fmaf(p, f, 6.931471805599453e-1f);
    p = fmaf(p, f, 1.0f);
    return __int_as_float(__float_as_int(p) + (i << 23));
}

// pack two floats -> bf16x2 (lo = first arg)
static __device__ __forceinline__ unsigned packbf(float lo, float hi) {
    unsigned u;
    asm("cvt.rn.bf16x2.f32 %0, %1, %2;" : "=r"(u) : "f"(hi), "f"(lo));
    return u;
}

static __device__ __forceinline__ void mma16816(float d[4], const unsigned a[4], const unsigned b[2]) {
    asm("mma.sync.aligned.m16n8k16.row.col.f32.bf16.bf16.f32 "
        "{%0,%1,%2,%3}, {%4,%5,%6,%7}, {%8,%9}, {%0,%1,%2,%3};"
        : "+f"(d[0]), "+f"(d[1]), "+f"(d[2]), "+f"(d[3])
        : "r"(a[0]), "r"(a[1]), "r"(a[2]), "r"(a[3]), "r"(b[0]), "r"(b[1]));
}

// ---------------- K1: qT = (W@x + bias) * 32^-0.25 (bf16), zero Z ----------------
__global__ void k1_qproj(const float* __restrict__ x, const float* __restrict__ W,
                         const float* __restrict__ bias) {
    __shared__ float sW[CR_ * 64];
    __shared__ float sb[CR_];
    int tid = threadIdx.x;
    for (int i = tid; i < CR_ * 64; i += 256) sW[i] = W[i];
    if (tid < CR_) sb[tid] = bias[tid];
    __syncthreads();

    int n = blockIdx.x * 256 + tid;
    float q[CR_];
#pragma unroll
    for (int k = 0; k < CR_; k++) q[k] = sb[k];
#pragma unroll 4
    for (int c = 0; c < 64; c++) {
        float xv = x[c * N_TOK + n];
#pragma unroll
        for (int k = 0; k < CR_; k++) q[k] = fmaf(sW[k * 64 + c], xv, q[k]);
    }
    const float sc = 0.42044820762685725f;  // 32^-0.25 (folds 1/sqrt(32) into qT*qT)
    unsigned* dst = g_qT + n * 16;
#pragma unroll
    for (int k = 0; k < 16; k++) dst[k] = packbf(q[2 * k] * sc, q[2 * k + 1] * sc);
    g_Z[n] = 0.0f;
}

// ---------------- K2: E = exp(qT . qT^T), Z = rowsum(E) ----------------
// grid (64 j-tiles, 64 i-tiles), 256 threads, warp tile 64x32, CTA tile 128x128
__global__ void __launch_bounds__(256, 1) k2_scores() {
    const int l = threadIdx.x & 31, w = threadIdx.x >> 5;
    const int g = l >> 2, t = l & 3;
    const int wm = w >> 2, wn = w & 3;
    const int i0 = blockIdx.y * 128 + wm * 64;
    const int j0 = blockIdx.x * 128 + wn * 32;

    unsigned a[4][2][4];
#pragma unroll
    for (int mi = 0; mi < 4; mi++)
#pragma unroll
        for (int kk = 0; kk < 2; kk++) {
            const unsigned* p = g_qT + (i0 + mi * 16 + g) * 16 + kk * 8 + t;
            a[mi][kk][0] = p[0];
            a[mi][kk][1] = p[128];      // +8 rows
            a[mi][kk][2] = p[4];        // +8 cols
            a[mi][kk][3] = p[132];
        }
    unsigned b[4][2][2];
#pragma unroll
    for (int ni = 0; ni < 4; ni++)
#pragma unroll
        for (int kk = 0; kk < 2; kk++) {
            const unsigned* p = g_qT + (j0 + ni * 8 + g) * 16 + kk * 8 + t;
            b[ni][kk][0] = p[0];
            b[ni][kk][1] = p[4];
        }

    float acc[4][4][4];
#pragma unroll
    for (int mi = 0; mi < 4; mi++)
#pragma unroll
        for (int ni = 0; ni < 4; ni++) {
            acc[mi][ni][0] = acc[mi][ni][1] = acc[mi][ni][2] = acc[mi][ni][3] = 0.0f;
#pragma unroll
            for (int kk = 0; kk < 2; kk++) mma16816(acc[mi][ni], a[mi][kk], b[ni][kk]);
        }

    float rs[4][2];
#pragma unroll
    for (int mi = 0; mi < 4; mi++) { rs[mi][0] = 0.0f; rs[mi][1] = 0.0f; }

#pragma unroll
    for (int mi = 0; mi < 4; mi++)
#pragma unroll
        for (int ni = 0; ni < 4; ni++) {
            float e0 = fexp(acc[mi][ni][0]);
            float e1 = fexp(acc[mi][ni][1]);
            float e2 = fexp(acc[mi][ni][2]);
            float e3 = fexp(acc[mi][ni][3]);
            rs[mi][0] += e0 + e1;
            rs[mi][1] += e2 + e3;
            size_t base = (size_t)(i0 + mi * 16 + g) * 4096 + ((j0 + ni * 8 + 2 * t) >> 1);
            g_E[base]                      = packbf(e0, e1);
            g_E[base + (size_t)8 * 4096]   = packbf(e2, e3);
        }

#pragma unroll
    for (int mi = 0; mi < 4; mi++)
#pragma unroll
        for (int r = 0; r < 2; r++) {
            float v = rs[mi][r];
            v += __shfl_xor_sync(0xffffffffu, v, 1);
            v += __shfl_xor_sync(0xffffffffu, v, 2);
            if (t == 0) atomicAdd(&g_Z[i0 + mi * 16 + r * 8 + g], v);
        }
}

// ---------------- K2b: vp[c][n] = bf16(x[c][n] / Z[n]) ----------------
__global__ void k2b_vprep(const float* __restrict__ x) {
    int wdx = blockIdx.x * 256 + threadIdx.x;  // word index, 0..262143
    int c  = wdx >> 12;
    int nw = wdx & 4095;
    int n  = nw * 2;
    float v0 = x[c * N_TOK + n]     / g_Z[n];
    float v1 = x[c * N_TOK + n + 1] / g_Z[n + 1];
    g_vp[wdx] = packbf(v0, v1);
}

// ---------------- K3: P[s] = vp @ E (split-K over n), out tile 64x128/CTA ----------------
// grid (64 m-tiles, 8 splits), 256 threads, warp tile 16(c) x 64(m)
// B-operand needs E^T rows; E is symmetric so E rows work directly.
__global__ void __launch_bounds__(256, 1) k3_bmm() {
    const int l = threadIdx.x & 31, w = threadIdx.x >> 5;
    const int g = l >> 2, t = l & 3;
    const int wc = w & 3, wm = w >> 2;
    const int c0 = wc * 16;
    const int m0 = blockIdx.x * 128 + wm * 64;
    const int kbase = blockIdx.y * 1024;

    float acc[8][4];
#pragma unroll
    for (int ni = 0; ni < 8; ni++)
        acc[ni][0] = acc[ni][1] = acc[ni][2] = acc[ni][3] = 0.0f;

#pragma unroll 4
    for (int kk = 0; kk < 64; kk++) {
        const int cw = ((kbase + kk * 16) >> 1) + t;
        unsigned a[4];
        const unsigned* pa = g_vp + (c0 + g) * 4096 + cw;
        a[0] = pa[0];
        a[1] = pa[8 * 4096];
        a[2] = pa[4];
        a[3] = pa[8 * 4096 + 4];
#pragma unroll
        for (int ni = 0; ni < 8; ni++) {
            unsigned b[2];
            const unsigned* pb = g_E + (size_t)(m0 + ni * 8 + g) * 4096 + cw;
            b[0] = pb[0];
            b[1] = pb[4];
            mma16816(acc[ni], a, b);
        }
    }

    const int pbase = blockIdx.y * (C_CH * N_TOK);
#pragma unroll
    for (int ni = 0; ni < 8; ni++) {
        int m = m0 + ni * 8 + 2 * t;
        *(float2*)(g_P + pbase + (c0 + g) * N_TOK + m)     = make_float2(acc[ni][0], acc[ni][1]);
        *(float2*)(g_P + pbase + (c0 + g + 8) * N_TOK + m) = make_float2(acc[ni][2], acc[ni][3]);
    }
}

// ---------------- K4: out = x + sum_s P[s] ----------------
__global__ void k4_final(const float* __restrict__ x, float* __restrict__ out) {
    int idx = blockIdx.x * 256 + threadIdx.x;
    float s = x[idx];
#pragma unroll
    for (int sp = 0; sp < 8; sp++) s += g_P[sp * (C_CH * N_TOK) + idx];
    out[idx] = s;
}

extern "C" void kernel_launch(void* const* d_in, const int* in_sizes, int n_in,
                              void* d_out, int out_size) {
    const float* x    = (const float*)d_in[0];   // [1,64,8,32,32] = [64][8192]
    const float* W    = (const float*)d_in[1];   // [32][64]
    const float* bias = (const float*)d_in[2];   // [32]
    float* out = (float*)d_out;                  // [64][8192]

    k1_qproj<<<32, 256>>>(x, W, bias);
    k2_scores<<<dim3(64, 64), 256>>>();
    k2b_vprep<<<1024, 256>>>(x);
    k3_bmm<<<dim3(64, 8), 256>>>();
    k4_final<<<2048, 256>>>(x, out);
}

// round 2
// speedup vs baseline: 2.3552x; 2.3552x over previous
#include <cuda_runtime.h>
#include <cuda_bf16.h>
#include <cstdint>

#define N_TOK 8192
#define C_CH  64
#define CR_   32
#define NSPLIT 4

// Scratch (static __device__ allocation is the sanctioned scratch mechanism)
__device__ unsigned g_qT[N_TOK * 16];               // [8192][32] bf16, scaled by 32^-0.25
__device__ unsigned g_E[(size_t)N_TOK * 4096];      // [8192][8192] bf16 = exp(S)
__device__ float    g_Z[N_TOK];                     // row sums of exp(S)
__device__ unsigned g_vp[C_CH * 4096];              // [64][8192] bf16 = x / Z[n]
__device__ __align__(16) float g_P[NSPLIT * C_CH * N_TOK];  // split-K partials (8MB)

// ---------------- helpers ----------------

// fast exp: exp(x) = 2^(x*log2e), magic-number rounding + deg-5 poly, FMA-pipe only
static __device__ __forceinline__ float fexp(float x) {
    float y = x * 1.44269504088896341f;
    float r = y + 12582912.0f;
    int   i = __float_as_int(r) - 0x4B400000;
    float f = y - (r - 12582912.0f);
    float p =               1.3333558146428443e-3f;
    p = fmaf(p, f, 9.618129842071803e-3f);
    p = fmaf(p, f, 5.550410866482158e-2f);
    p = fmaf(p, f, 2.402265069591007e-1f);
    p = fmaf(p, f, 6.931471805599453e-1f);
    p = fmaf(p, f, 1.0f);
    return __int_as_float(__float_as_int(p) + (i << 23));
}

static __device__ __forceinline__ unsigned packbf(float lo, float hi) {
    unsigned u;
    asm("cvt.rn.bf16x2.f32 %0, %1, %2;" : "=r"(u) : "f"(hi), "f"(lo));
    return u;
}

static __device__ __forceinline__ void mma16816(float d[4], const unsigned a[4], const unsigned b[2]) {
    asm("mma.sync.aligned.m16n8k16.row.col.f32.bf16.bf16.f32 "
        "{%0,%1,%2,%3}, {%4,%5,%6,%7}, {%8,%9}, {%0,%1,%2,%3};"
        : "+f"(d[0]), "+f"(d[1]), "+f"(d[2]), "+f"(d[3])
        : "r"(a[0]), "r"(a[1]), "r"(a[2]), "r"(a[3]), "r"(b[0]), "r"(b[1]));
}

static __device__ __forceinline__ void ldsm4(unsigned& r0, unsigned& r1, unsigned& r2, unsigned& r3,
                                             unsigned saddr) {
    asm volatile("ldmatrix.sync.aligned.m8n8.x4.shared.b16 {%0,%1,%2,%3}, [%4];"
                 : "=r"(r0), "=r"(r1), "=r"(r2), "=r"(r3) : "r"(saddr));
}

static __device__ __forceinline__ void cpasync16(unsigned saddr, const void* gsrc) {
    asm volatile("cp.async.cg.shared.global [%0], [%1], 16;" :: "r"(saddr), "l"(gsrc));
}

// ---------------- K1: qT = (W@x + bias) * 32^-0.25 (bf16), zero Z ----------------
__global__ void k1_qproj(const float* __restrict__ x, const float* __restrict__ W,
                         const float* __restrict__ bias) {
    __shared__ float sW[CR_ * 64];
    __shared__ float sb[CR_];
    int tid = threadIdx.x;
    for (int i = tid; i < CR_ * 64; i += 256) sW[i] = W[i];
    if (tid < CR_) sb[tid] = bias[tid];
    __syncthreads();

    int n = blockIdx.x * 256 + tid;
    float q[CR_];
#pragma unroll
    for (int k = 0; k < CR_; k++) q[k] = sb[k];
#pragma unroll 4
    for (int c = 0; c < 64; c++) {
        float xv = x[c * N_TOK + n];
#pragma unroll
        for (int k = 0; k < CR_; k++) q[k] = fmaf(sW[k * 64 + c], xv, q[k]);
    }
    const float sc = 0.42044820762685725f;  // 32^-0.25
    unsigned* dst = g_qT + n * 16;
#pragma unroll
    for (int k = 0; k < 16; k++) dst[k] = packbf(q[2 * k] * sc, q[2 * k + 1] * sc);
    g_Z[n] = 0.0f;
}

// ---------------- K2: E = exp(qT . qT^T), Z = rowsum(E) ----------------
// grid (64 j-tiles, 64 i-tiles), 256 threads, CTA tile 128x128.
// Output staged through swizzled smem for fully coalesced 16B global stores.
__global__ void __launch_bounds__(256, 1) k2_scores() {
    __shared__ __align__(16) unsigned sE[128 * 64];  // 32 KB, [row][64 words], word-swizzled
    const int l = threadIdx.x & 31, w = threadIdx.x >> 5;
    const int g = l >> 2, t = l & 3;
    const int wm = w >> 2, wn = w & 3;
    const int i0 = blockIdx.y * 128 + wm * 64;
    const int j0 = blockIdx.x * 128 + wn * 32;

    unsigned a[4][2][4];
#pragma unroll
    for (int mi = 0; mi < 4; mi++)
#pragma unroll
        for (int kk = 0; kk < 2; kk++) {
            const unsigned* p = g_qT + (i0 + mi * 16 + g) * 16 + kk * 8 + t;
            a[mi][kk][0] = p[0];
            a[mi][kk][1] = p[128];
            a[mi][kk][2] = p[4];
            a[mi][kk][3] = p[132];
        }
    unsigned b[4][2][2];
#pragma unroll
    for (int ni = 0; ni < 4; ni++)
#pragma unroll
        for (int kk = 0; kk < 2; kk++) {
            const unsigned* p = g_qT + (j0 + ni * 8 + g) * 16 + kk * 8 + t;
            b[ni][kk][0] = p[0];
            b[ni][kk][1] = p[4];
        }

    float acc[4][4][4];
#pragma unroll
    for (int mi = 0; mi < 4; mi++)
#pragma unroll
        for (int ni = 0; ni < 4; ni++) {
            acc[mi][ni][0] = acc[mi][ni][1] = acc[mi][ni][2] = acc[mi][ni][3] = 0.0f;
#pragma unroll
            for (int kk = 0; kk < 2; kk++) mma16816(acc[mi][ni], a[mi][kk], b[ni][kk]);
        }

    float rs[4][2];
#pragma unroll
    for (int mi = 0; mi < 4; mi++) { rs[mi][0] = 0.0f; rs[mi][1] = 0.0f; }

#pragma unroll
    for (int mi = 0; mi < 4; mi++)
#pragma unroll
        for (int ni = 0; ni < 4; ni++) {
            float e0 = fexp(acc[mi][ni][0]);
            float e1 = fexp(acc[mi][ni][1]);
            float e2 = fexp(acc[mi][ni][2]);
            float e3 = fexp(acc[mi][ni][3]);
            rs[mi][0] += e0 + e1;
            rs[mi][1] += e2 + e3;
            int cw = wn * 16 + ni * 4 + t;              // word col within 128-col tile
            int r0r = wm * 64 + mi * 16 + g;
            int r1r = r0r + 8;
            sE[r0r * 64 + (cw ^ ((r0r & 7) << 3))] = packbf(e0, e1);
            sE[r1r * 64 + (cw ^ ((r1r & 7) << 3))] = packbf(e2, e3);
        }

#pragma unroll
    for (int mi = 0; mi < 4; mi++)
#pragma unroll
        for (int r = 0; r < 2; r++) {
            float v = rs[mi][r];
            v += __shfl_xor_sync(0xffffffffu, v, 1);
            v += __shfl_xor_sync(0xffffffffu, v, 2);
            if (t == 0) atomicAdd(&g_Z[i0 + mi * 16 + r * 8 + g], v);
        }

    __syncthreads();
    // coalesced copy smem -> global: 2048 x 16B chunks
#pragma unroll
    for (int it = 0; it < 8; it++) {
        int idx = it * 256 + threadIdx.x;
        int r = idx >> 4, c16 = idx & 15;
        unsigned sidx = r * 64 + ((c16 * 4) ^ ((r & 7) << 3));
        unsigned* dst = g_E + (size_t)(blockIdx.y * 128 + r) * 4096 + blockIdx.x * 64 + c16 * 4;
        *(uint4*)dst = *(const uint4*)(sE + sidx);
    }
}

// ---------------- K2b: vp[c][n] = bf16(x[c][n] / Z[n]) ----------------
__global__ void k2b_vprep(const float* __restrict__ x) {
    int wdx = blockIdx.x * 256 + threadIdx.x;
    int c  = wdx >> 12;
    int nw = wdx & 4095;
    int n  = nw * 2;
    float v0 = x[c * N_TOK + n]     / g_Z[n];
    float v1 = x[c * N_TOK + n + 1] / g_Z[n + 1];
    g_vp[wdx] = packbf(v0, v1);
}

// ---------------- K3: P[s] = vp @ E (split-K), smem-pipelined GEMM ----------------
// grid (64 m-tiles, 4 splits), 256 threads. CTA tile 64(c) x 128(m), KC=64.
// Double-buffered cp.async staging, ldmatrix fragments, XOR-8 swizzle.
// B-operand needs E^T rows; E symmetric -> rows of E.
__global__ void __launch_bounds__(256, 1) k3_bmm() {
    __shared__ __align__(16) unsigned sA[2][64 * 32];    // 16 KB (2 bufs)
    __shared__ __align__(16) unsigned sB[2][128 * 32];   // 32 KB (2 bufs)
    const int tid = threadIdx.x;
    const int l = tid & 31, w = tid >> 5;
    const int g = l >> 2, t = l & 3;
    const int wc = w >> 2, wm = w & 3;            // 2 c-warps x 4 m-warps
    const int mtile = blockIdx.x;
    const int kw0 = blockIdx.y * 1024;            // word offset into 4096-word rows

    const unsigned sAb = (unsigned)__cvta_generic_to_shared(&sA[0][0]);
    const unsigned sBb = (unsigned)__cvta_generic_to_shared(&sB[0][0]);

    float acc[2][4][4];
#pragma unroll
    for (int mi = 0; mi < 2; mi++)
#pragma unroll
        for (int ni = 0; ni < 4; ni++)
            acc[mi][ni][0] = acc[mi][ni][1] = acc[mi][ni][2] = acc[mi][ni][3] = 0.0f;

    auto issue = [&](int buf, int ch) {
        int kw = kw0 + ch * 32;                   // 64 bf16 = 32 words per chunk
        unsigned sAbuf = sAb + buf * (64 * 32 * 4);
        unsigned sBbuf = sBb + buf * (128 * 32 * 4);
#pragma unroll
        for (int it = 0; it < 2; it++) {          // A: 64 rows x 8 chunks
            int idx = it * 256 + tid;
            int r = idx >> 3, c = idx & 7;
            cpasync16(sAbuf + (r * 32 + ((c ^ (r & 7)) << 2)) * 4,
                      g_vp + r * 4096 + kw + c * 4);
        }
#pragma unroll
        for (int it = 0; it < 4; it++) {          // B: 128 rows x 8 chunks
            int idx = it * 256 + tid;
            int r = idx >> 3, c = idx & 7;
            cpasync16(sBbuf + (r * 32 + ((c ^ (r & 7)) << 2)) * 4,
                      g_E + (size_t)(mtile * 128 + r) * 4096 + kw + c * 4);
        }
        asm volatile("cp.async.commit_group;" ::);
    };

    auto compute = [&](int buf) {
        unsigned sAbuf = sAb + buf * (64 * 32 * 4);
        unsigned sBbuf = sBb + buf * (128 * 32 * 4);
#pragma unroll
        for (int kk = 0; kk < 4; kk++) {
            int ch = kk * 2 + (l >> 4);           // 16B chunk index for ldmatrix
            unsigned a[2][4], b[2][4];
#pragma unroll
            for (int mi = 0; mi < 2; mi++) {
                int r = wc * 32 + mi * 16 + (l & 15);
                ldsm4(a[mi][0], a[mi][1], a[mi][2], a[mi][3],
                      sAbuf + (r * 32 + ((ch ^ (r & 7)) << 2)) * 4);
            }
#pragma unroll
            for (int np = 0; np < 2; np++) {
                int r = wm * 32 + np * 16 + (l & 15);
                ldsm4(b[np][0], b[np][1], b[np][2], b[np][3],
                      sBbuf + (r * 32 + ((ch ^ (r & 7)) << 2)) * 4);
            }
#pragma unroll
            for (int mi = 0; mi < 2; mi++)
#pragma unroll
                for (int np = 0; np < 2; np++) {
                    unsigned b0[2] = {b[np][0], b[np][2]};
                    unsigned b1[2] = {b[np][1], b[np][3]};
                    mma16816(acc[mi][np * 2],     a[mi], b0);
                    mma16816(acc[mi][np * 2 + 1], a[mi], b1);
                }
        }
    };

    issue(0, 0);
    for (int ch = 0; ch < 32; ch++) {
        if (ch < 31) {
            issue((ch + 1) & 1, ch + 1);
            asm volatile("cp.async.wait_group 1;" ::);
        } else {
            asm volatile("cp.async.wait_group 0;" ::);
        }
        __syncthreads();
        compute(ch & 1);
        __syncthreads();
    }

    const int pbase = blockIdx.y * (C_CH * N_TOK);
#pragma unroll
    for (int mi = 0; mi < 2; mi++)
#pragma unroll
        for (int ni = 0; ni < 4; ni++) {
            int c = wc * 32 + mi * 16 + g;
            int m = mtile * 128 + wm * 32 + ni * 8 + 2 * t;
            *(float2*)(g_P + pbase + c * N_TOK + m)       = make_float2(acc[mi][ni][0], acc[mi][ni][1]);
            *(float2*)(g_P + pbase + (c + 8) * N_TOK + m) = make_float2(acc[mi][ni][2], acc[mi][ni][3]);
        }
}

// ---------------- K4: out = x + sum_s P[s] ----------------
__global__ void k4_final(const float* __restrict__ x, float* __restrict__ out) {
    int idx = blockIdx.x * 256 + threadIdx.x;
    float s = x[idx];
#pragma unroll
    for (int sp = 0; sp < NSPLIT; sp++) s += g_P[sp * (C_CH * N_TOK) + idx];
    out[idx] = s;
}

extern "C" void kernel_launch(void* const* d_in, const int* in_sizes, int n_in,
                              void* d_out, int out_size) {
    const float* x    = (const float*)d_in[0];   // [1,64,8,32,32] = [64][8192]
    const float* W    = (const float*)d_in[1];   // [32][64]
    const float* bias = (const float*)d_in[2];   // [32]
    float* out = (float*)d_out;                  // [64][8192]

    k1_qproj<<<32, 256>>>(x, W, bias);
    k2_scores<<<dim3(64, 64), 256>>>();
    k2b_vprep<<<1024, 256>>>(x);
    k3_bmm<<<dim3(64, NSPLIT), 256>>>();
    k4_final<<<2048, 256>>>(x, out);
}

// round 3
// speedup vs baseline: 2.5106x; 1.0660x over previous
#include <cuda_runtime.h>
#include <cuda_bf16.h>
#include <cstdint>

#define N_TOK 8192
#define C_CH  64
#define CR_   32
#define NSPLIT 2

// Scratch
__device__ unsigned g_qT[N_TOK * 16];               // [8192][32] bf16, scaled by 32^-0.25
__device__ float    g_Z[N_TOK];                     // row sums of exp(S)
__device__ unsigned g_vp[C_CH * 4096];              // [64][8192] bf16 = x / Z[n]
__device__ __align__(16) float g_P[NSPLIT * C_CH * N_TOK];  // split partials (4MB)

// ---------------- helpers ----------------
static __device__ __forceinline__ float fexp(float x) {
    float y = x * 1.44269504088896341f;
    float r = y + 12582912.0f;
    int   i = __float_as_int(r) - 0x4B400000;
    float f = y - (r - 12582912.0f);
    float p =               1.3333558146428443e-3f;
    p = fmaf(p, f, 9.618129842071803e-3f);
    p = fmaf(p, f, 5.550410866482158e-2f);
    p = fmaf(p, f, 2.402265069591007e-1f);
    p = fmaf(p, f, 6.931471805599453e-1f);
    p = fmaf(p, f, 1.0f);
    return __int_as_float(__float_as_int(p) + (i << 23));
}

static __device__ __forceinline__ unsigned packbf(float lo, float hi) {
    unsigned u;
    asm("cvt.rn.bf16x2.f32 %0, %1, %2;" : "=r"(u) : "f"(hi), "f"(lo));
    return u;
}

static __device__ __forceinline__ void mma16816(float d[4], const unsigned a[4], const unsigned b[2]) {
    asm("mma.sync.aligned.m16n8k16.row.col.f32.bf16.bf16.f32 "
        "{%0,%1,%2,%3}, {%4,%5,%6,%7}, {%8,%9}, {%0,%1,%2,%3};"
        : "+f"(d[0]), "+f"(d[1]), "+f"(d[2]), "+f"(d[3])
        : "r"(a[0]), "r"(a[1]), "r"(a[2]), "r"(a[3]), "r"(b[0]), "r"(b[1]));
}

static __device__ __forceinline__ void ldsm4(unsigned& r0, unsigned& r1, unsigned& r2, unsigned& r3,
                                             unsigned saddr) {
    asm volatile("ldmatrix.sync.aligned.m8n8.x4.shared.b16 {%0,%1,%2,%3}, [%4];"
                 : "=r"(r0), "=r"(r1), "=r"(r2), "=r"(r3) : "r"(saddr));
}

static __device__ __forceinline__ void cpasync16(unsigned saddr, const void* gsrc) {
    asm volatile("cp.async.cg.shared.global [%0], [%1], 16;" :: "r"(saddr), "l"(gsrc));
}

// word-level swizzle consistent with 16B-chunk XOR: chunk = w>>2, chunk ^= (r&7)
static __device__ __forceinline__ int swz(int r, int w) {
    return (((w >> 2) ^ (r & 7)) << 2) | (w & 3);
}

// ---------------- K1: qT = (W@x + bias) * 32^-0.25, zero Z ----------------
__global__ void k1_qproj(const float* __restrict__ x, const float* __restrict__ W,
                         const float* __restrict__ bias) {
    __shared__ float sW[CR_ * 64];
    __shared__ float sb[CR_];
    int tid = threadIdx.x;
    for (int i = tid; i < CR_ * 64; i += 256) sW[i] = W[i];
    if (tid < CR_) sb[tid] = bias[tid];
    __syncthreads();

    int n = blockIdx.x * 256 + tid;
    float q[CR_];
#pragma unroll
    for (int k = 0; k < CR_; k++) q[k] = sb[k];
#pragma unroll 4
    for (int c = 0; c < 64; c++) {
        float xv = x[c * N_TOK + n];
#pragma unroll
        for (int k = 0; k < CR_; k++) q[k] = fmaf(sW[k * 64 + c], xv, q[k]);
    }
    const float sc = 0.42044820762685725f;  // 32^-0.25
    unsigned* dst = g_qT + n * 16;
#pragma unroll
    for (int k = 0; k < 16; k++) dst[k] = packbf(q[2 * k] * sc, q[2 * k + 1] * sc);
    g_Z[n] = 0.0f;
}

// ---------------- KA: Z = rowsum(exp(S)), symmetric (tiles tj>=ti only) ----------------
// For off-diagonal tile (i0,j0): rowsums -> Z[i], colsums -> Z[j] (colsum == rowsum of
// the mirrored tile by symmetry). Diagonal tiles: rowsums only.
__global__ void __launch_bounds__(256, 1) kA_zsum() {
    if (blockIdx.x < blockIdx.y) return;   // only tj >= ti
    const int l = threadIdx.x & 31, w = threadIdx.x >> 5;
    const int g = l >> 2, t = l & 3;
    const int wm = w >> 2, wn = w & 3;
    const int i0 = blockIdx.y * 128 + wm * 64;
    const int j0 = blockIdx.x * 128 + wn * 32;

    unsigned a[4][2][4];
#pragma unroll
    for (int mi = 0; mi < 4; mi++)
#pragma unroll
        for (int kk = 0; kk < 2; kk++) {
            const unsigned* p = g_qT + (i0 + mi * 16 + g) * 16 + kk * 8 + t;
            a[mi][kk][0] = p[0];
            a[mi][kk][1] = p[128];
            a[mi][kk][2] = p[4];
            a[mi][kk][3] = p[132];
        }
    unsigned b[4][2][2];
#pragma unroll
    for (int ni = 0; ni < 4; ni++)
#pragma unroll
        for (int kk = 0; kk < 2; kk++) {
            const unsigned* p = g_qT + (j0 + ni * 8 + g) * 16 + kk * 8 + t;
            b[ni][kk][0] = p[0];
            b[ni][kk][1] = p[4];
        }

    float acc[4][4][4];
#pragma unroll
    for (int mi = 0; mi < 4; mi++)
#pragma unroll
        for (int ni = 0; ni < 4; ni++) {
            acc[mi][ni][0] = acc[mi][ni][1] = acc[mi][ni][2] = acc[mi][ni][3] = 0.0f;
#pragma unroll
            for (int kk = 0; kk < 2; kk++) mma16816(acc[mi][ni], a[mi][kk], b[ni][kk]);
        }

    float rs[4][2];
    float cs[4][2];
#pragma unroll
    for (int i = 0; i < 4; i++) { rs[i][0] = rs[i][1] = 0.0f; cs[i][0] = cs[i][1] = 0.0f; }

#pragma unroll
    for (int mi = 0; mi < 4; mi++)
#pragma unroll
        for (int ni = 0; ni < 4; ni++) {
            float e0 = fexp(acc[mi][ni][0]);
            float e1 = fexp(acc[mi][ni][1]);
            float e2 = fexp(acc[mi][ni][2]);
            float e3 = fexp(acc[mi][ni][3]);
            rs[mi][0] += e0 + e1;
            rs[mi][1] += e2 + e3;
            cs[ni][0] += e0 + e2;   // col 2t
            cs[ni][1] += e1 + e3;   // col 2t+1
        }

    // row sums -> Z[i]
#pragma unroll
    for (int mi = 0; mi < 4; mi++)
#pragma unroll
        for (int r = 0; r < 2; r++) {
            float v = rs[mi][r];
            v += __shfl_xor_sync(0xffffffffu, v, 1);
            v += __shfl_xor_sync(0xffffffffu, v, 2);
            if (t == 0) atomicAdd(&g_Z[i0 + mi * 16 + r * 8 + g], v);
        }

    // col sums -> Z[j] (skip on diagonal tiles: already counted by rowsums)
    if (blockIdx.x != blockIdx.y) {
#pragma unroll
        for (int ni = 0; ni < 4; ni++)
#pragma unroll
            for (int p = 0; p < 2; p++) {
                float v = cs[ni][p];
                v += __shfl_xor_sync(0xffffffffu, v, 4);
                v += __shfl_xor_sync(0xffffffffu, v, 8);
                v += __shfl_xor_sync(0xffffffffu, v, 16);
                if (l < 4) atomicAdd(&g_Z[j0 + ni * 8 + 2 * t + p], v);
            }
    }
}

// ---------------- K2b: vp[c][n] = bf16(x[c][n] / Z[n]) ----------------
__global__ void k2b_vprep(const float* __restrict__ x) {
    int wdx = blockIdx.x * 256 + threadIdx.x;
    int c  = wdx >> 12;
    int nw = wdx & 4095;
    int n  = nw * 2;
    float v0 = x[c * N_TOK + n]     / g_Z[n];
    float v1 = x[c * N_TOK + n + 1] / g_Z[n + 1];
    g_vp[wdx] = packbf(v0, v1);
}

// ---------------- KB: fused E-recompute + out GEMM ----------------
// grid (64 m-tiles, NSPLIT). Per iter (n-tile of 128):
//   phase1: S block = qT(m rows) x qT(n rows) via mma; exp -> bf16 -> swizzled sE
//   phase2: out[c,m] += vp[c,n-tile] @ sE  (A via ldmatrix from cp.async-staged sVP,
//           B via ldmatrix from sE; E symmetric so sE rows m serve as B^T rows)
__global__ void __launch_bounds__(256, 1) kB_fused() {
    __shared__ __align__(16) unsigned sE[128 * 64];      // 32 KB  [m local][64 words]
    __shared__ __align__(16) unsigned sVP[2][64 * 64];   // 32 KB  [c][64 words] x2
    const int tid = threadIdx.x;
    const int l = tid & 31, w = tid >> 5;
    const int g = l >> 2, t = l & 3;
    const int wm = w >> 2, wn = w & 3;    // phase1: 2 m-groups x 4 n-groups
    const int wc = w >> 2, wm2 = w & 3;   // phase2: 2 c-groups x 4 m-groups
    const int m0 = blockIdx.x * 128;

    const unsigned sEb  = (unsigned)__cvta_generic_to_shared(&sE[0]);
    const unsigned sVPb = (unsigned)__cvta_generic_to_shared(&sVP[0][0]);

    // preload A fragments (qT rows of this m-tile) — constant across iterations
    unsigned ap[4][2][4];
#pragma unroll
    for (int mi = 0; mi < 4; mi++)
#pragma unroll
        for (int kk = 0; kk < 2; kk++) {
            const unsigned* p = g_qT + (m0 + wm * 64 + mi * 16 + g) * 16 + kk * 8 + t;
            ap[mi][kk][0] = p[0];
            ap[mi][kk][1] = p[128];
            ap[mi][kk][2] = p[4];
            ap[mi][kk][3] = p[132];
        }

    float out[2][4][4];
#pragma unroll
    for (int ci = 0; ci < 2; ci++)
#pragma unroll
        for (int ni = 0; ni < 4; ni++)
            out[ci][ni][0] = out[ci][ni][1] = out[ci][ni][2] = out[ci][ni][3] = 0.0f;

    auto issueVP = [&](int buf, int nt) {
        // 64 rows x 16 chunks of 16B = 1024 chunks, 4 per thread
#pragma unroll
        for (int it = 0; it < 4; it++) {
            int idx = it * 256 + tid;
            int r = idx >> 4, c = idx & 15;
            cpasync16(sVPb + (buf * 4096 + r * 64 + ((c ^ (r & 7)) << 2)) * 4,
                      g_vp + r * 4096 + nt * 64 + c * 4);
        }
        asm volatile("cp.async.commit_group;" ::);
    };

    const int ntbase = blockIdx.y * 32;
    issueVP(0, ntbase);

    for (int it = 0; it < 32; it++) {
        const int nt = ntbase + it;
        const int n0 = nt * 128;
        if (it < 31) issueVP((it + 1) & 1, nt + 1);

        // ---- phase 1: S block + exp -> sE ----
        unsigned b[4][2][2];
#pragma unroll
        for (int ni = 0; ni < 4; ni++)
#pragma unroll
            for (int kk = 0; kk < 2; kk++) {
                const unsigned* p = g_qT + (n0 + wn * 32 + ni * 8 + g) * 16 + kk * 8 + t;
                b[ni][kk][0] = p[0];
                b[ni][kk][1] = p[4];
            }
        float acc1[4][4][4];
#pragma unroll
        for (int mi = 0; mi < 4; mi++)
#pragma unroll
            for (int ni = 0; ni < 4; ni++) {
                acc1[mi][ni][0] = acc1[mi][ni][1] = acc1[mi][ni][2] = acc1[mi][ni][3] = 0.0f;
#pragma unroll
                for (int kk = 0; kk < 2; kk++) mma16816(acc1[mi][ni], ap[mi][kk], b[ni][kk]);
            }

#pragma unroll
        for (int mi = 0; mi < 4; mi++)
#pragma unroll
            for (int ni = 0; ni < 4; ni++) {
                float e0 = fexp(acc1[mi][ni][0]);
                float e1 = fexp(acc1[mi][ni][1]);
                float e2 = fexp(acc1[mi][ni][2]);
                float e3 = fexp(acc1[mi][ni][3]);
                int cw = wn * 16 + ni * 4 + t;
                int r0 = wm * 64 + mi * 16 + g;
                int r1 = r0 + 8;
                sE[r0 * 64 + swz(r0, cw)] = packbf(e0, e1);
                sE[r1 * 64 + swz(r1, cw)] = packbf(e2, e3);
            }

        __syncthreads();
        if (it < 31) { asm volatile("cp.async.wait_group 1;" ::); }
        else         { asm volatile("cp.async.wait_group 0;" ::); }

        // ---- phase 2: out += vp @ sE ----
        const unsigned vbuf = sVPb + (unsigned)((it & 1) * 4096 * 4);
#pragma unroll
        for (int kk = 0; kk < 8; kk++) {
            int chk = kk * 2 + (l >> 4);
            unsigned a2[2][4], b2[2][4];
#pragma unroll
            for (int ci = 0; ci < 2; ci++) {
                int r = wc * 32 + ci * 16 + (l & 15);
                ldsm4(a2[ci][0], a2[ci][1], a2[ci][2], a2[ci][3],
                      vbuf + (r * 64 + ((chk ^ (r & 7)) << 2)) * 4);
            }
#pragma unroll
            for (int np = 0; np < 2; np++) {
                int r = wm2 * 32 + np * 16 + (l & 15);
                ldsm4(b2[np][0], b2[np][1], b2[np][2], b2[np][3],
                      sEb + (r * 64 + ((chk ^ (r & 7)) << 2)) * 4);
            }
#pragma unroll
            for (int ci = 0; ci < 2; ci++)
#pragma unroll
                for (int np = 0; np < 2; np++) {
                    unsigned bl[2] = {b2[np][0], b2[np][2]};
                    unsigned bh[2] = {b2[np][1], b2[np][3]};
                    mma16816(out[ci][np * 2],     a2[ci], bl);
                    mma16816(out[ci][np * 2 + 1], a2[ci], bh);
                }
        }
        __syncthreads();
    }

    // epilogue: partials
    float* P = g_P + blockIdx.y * (C_CH * N_TOK);
#pragma unroll
    for (int ci = 0; ci < 2; ci++)
#pragma unroll
        for (int ni = 0; ni < 4; ni++) {
            int c = wc * 32 + ci * 16 + g;
            int m = m0 + wm2 * 32 + ni * 8 + 2 * t;
            *(float2*)(P + c * N_TOK + m)       = make_float2(out[ci][ni][0], out[ci][ni][1]);
            *(float2*)(P + (c + 8) * N_TOK + m) = make_float2(out[ci][ni][2], out[ci][ni][3]);
        }
}

// ---------------- K4: out = x + sum_s P[s] ----------------
__global__ void k4_final(const float* __restrict__ x, float* __restrict__ out) {
    int idx = blockIdx.x * 256 + threadIdx.x;
    float s = x[idx];
#pragma unroll
    for (int sp = 0; sp < NSPLIT; sp++) s += g_P[sp * (C_CH * N_TOK) + idx];
    out[idx] = s;
}

extern "C" void kernel_launch(void* const* d_in, const int* in_sizes, int n_in,
                              void* d_out, int out_size) {
    const float* x    = (const float*)d_in[0];   // [64][8192]
    const float* W    = (const float*)d_in[1];   // [32][64]
    const float* bias = (const float*)d_in[2];   // [32]
    float* out = (float*)d_out;                  // [64][8192]

    k1_qproj<<<32, 256>>>(x, W, bias);
    kA_zsum<<<dim3(64, 64), 256>>>();
    k2b_vprep<<<1024, 256>>>(x);
    kB_fused<<<dim3(64, NSPLIT), 256>>>();
    k4_final<<<2048, 256>>>(x, out);
}

// round 4
// speedup vs baseline: 2.6105x; 1.0398x over previous
#include <cuda_runtime.h>
#include <cuda_bf16.h>
#include <cstdint>

#define N_TOK 8192
#define C_CH  64
#define CR_   32
#define NSPLIT 2

// Scratch
__device__ unsigned g_qT[N_TOK * 16];               // [8192][32] bf16, scaled by sqrt(log2e)*32^-0.25
__device__ float    g_Z[N_TOK];                     // row sums of exp(S)
__device__ unsigned g_vp[C_CH * 4096];              // [64][8192] bf16 = x / Z[n]
__device__ __align__(16) float g_P[NSPLIT * C_CH * N_TOK];  // split partials (4MB)

// ---------------- helpers ----------------
// qT is pre-scaled so that qT.qT = S * log2(e) / sqrt(32) -> exp(S/sqrt32) = ex2(acc)
static __device__ __forceinline__ float ex2f(float x) {
    float r;
    asm("ex2.approx.f32 %0, %1;" : "=f"(r) : "f"(x));
    return r;
}

static __device__ __forceinline__ unsigned packbf(float lo, float hi) {
    unsigned u;
    asm("cvt.rn.bf16x2.f32 %0, %1, %2;" : "=r"(u) : "f"(hi), "f"(lo));
    return u;
}

static __device__ __forceinline__ void mma16816(float d[4], const unsigned a[4], const unsigned b[2]) {
    asm("mma.sync.aligned.m16n8k16.row.col.f32.bf16.bf16.f32 "
        "{%0,%1,%2,%3}, {%4,%5,%6,%7}, {%8,%9}, {%0,%1,%2,%3};"
        : "+f"(d[0]), "+f"(d[1]), "+f"(d[2]), "+f"(d[3])
        : "r"(a[0]), "r"(a[1]), "r"(a[2]), "r"(a[3]), "r"(b[0]), "r"(b[1]));
}

static __device__ __forceinline__ void ldsm4(unsigned& r0, unsigned& r1, unsigned& r2, unsigned& r3,
                                             unsigned saddr) {
    asm volatile("ldmatrix.sync.aligned.m8n8.x4.shared.b16 {%0,%1,%2,%3}, [%4];"
                 : "=r"(r0), "=r"(r1), "=r"(r2), "=r"(r3) : "r"(saddr));
}

static __device__ __forceinline__ void cpasync16(unsigned saddr, const void* gsrc) {
    asm volatile("cp.async.cg.shared.global [%0], [%1], 16;" :: "r"(saddr), "l"(gsrc));
}

static __device__ __forceinline__ int swz(int r, int w) {
    return (((w >> 2) ^ (r & 7)) << 2) | (w & 3);
}

// ---------------- K1: qT = (W@x + bias) * sqrt(log2e)*32^-0.25, zero Z ----------------
__global__ void k1_qproj(const float* __restrict__ x, const float* __restrict__ W,
                         const float* __restrict__ bias) {
    __shared__ float sW[CR_ * 64];
    __shared__ float sb[CR_];
    int tid = threadIdx.x;
    for (int i = tid; i < CR_ * 64; i += 256) sW[i] = W[i];
    if (tid < CR_) sb[tid] = bias[tid];
    __syncthreads();

    int n = blockIdx.x * 256 + tid;
    float q[CR_];
#pragma unroll
    for (int k = 0; k < CR_; k++) q[k] = sb[k];
#pragma unroll 4
    for (int c = 0; c < 64; c++) {
        float xv = x[c * N_TOK + n];
#pragma unroll
        for (int k = 0; k < CR_; k++) q[k] = fmaf(sW[k * 64 + c], xv, q[k]);
    }
    const float sc = 0.5050097687177836f;  // 32^-0.25 * sqrt(log2 e)
    unsigned* dst = g_qT + n * 16;
#pragma unroll
    for (int k = 0; k < 16; k++) dst[k] = packbf(q[2 * k] * sc, q[2 * k + 1] * sc);
    g_Z[n] = 0.0f;
}

// ---------------- KA: Z = rowsum(exp(S)), triangular launch (2080 CTAs) ----------------
__global__ void __launch_bounds__(256, 1) kA_zsum() {
    // map linear bid -> (ti, tj), ti <= tj, 64 tiles of 128
    const int bid = blockIdx.x;
    int ti = (int)((129.0f - sqrtf(16641.0f - 8.0f * (float)bid)) * 0.5f);
    while (ti > 0 && bid < (129 * ti - ti * ti) / 2) ti--;
    while (bid >= (129 * (ti + 1) - (ti + 1) * (ti + 1)) / 2) ti++;
    const int tj = ti + (bid - (129 * ti - ti * ti) / 2);

    const int l = threadIdx.x & 31, w = threadIdx.x >> 5;
    const int g = l >> 2, t = l & 3;
    const int wm = w >> 2, wn = w & 3;
    const int i0 = ti * 128 + wm * 64;
    const int j0 = tj * 128 + wn * 32;

    unsigned a[4][2][4];
#pragma unroll
    for (int mi = 0; mi < 4; mi++)
#pragma unroll
        for (int kk = 0; kk < 2; kk++) {
            const unsigned* p = g_qT + (i0 + mi * 16 + g) * 16 + kk * 8 + t;
            a[mi][kk][0] = p[0];
            a[mi][kk][1] = p[128];
            a[mi][kk][2] = p[4];
            a[mi][kk][3] = p[132];
        }
    unsigned b[4][2][2];
#pragma unroll
    for (int ni = 0; ni < 4; ni++)
#pragma unroll
        for (int kk = 0; kk < 2; kk++) {
            const unsigned* p = g_qT + (j0 + ni * 8 + g) * 16 + kk * 8 + t;
            b[ni][kk][0] = p[0];
            b[ni][kk][1] = p[4];
        }

    float acc[4][4][4];
#pragma unroll
    for (int mi = 0; mi < 4; mi++)
#pragma unroll
        for (int ni = 0; ni < 4; ni++) {
            acc[mi][ni][0] = acc[mi][ni][1] = acc[mi][ni][2] = acc[mi][ni][3] = 0.0f;
#pragma unroll
            for (int kk = 0; kk < 2; kk++) mma16816(acc[mi][ni], a[mi][kk], b[ni][kk]);
        }

    float rs[4][2];
    float cs[4][2];
#pragma unroll
    for (int i = 0; i < 4; i++) { rs[i][0] = rs[i][1] = 0.0f; cs[i][0] = cs[i][1] = 0.0f; }

#pragma unroll
    for (int mi = 0; mi < 4; mi++)
#pragma unroll
        for (int ni = 0; ni < 4; ni++) {
            float e0 = ex2f(acc[mi][ni][0]);
            float e1 = ex2f(acc[mi][ni][1]);
            float e2 = ex2f(acc[mi][ni][2]);
            float e3 = ex2f(acc[mi][ni][3]);
            rs[mi][0] += e0 + e1;
            rs[mi][1] += e2 + e3;
            cs[ni][0] += e0 + e2;
            cs[ni][1] += e1 + e3;
        }

    // row sums -> Z[i]
#pragma unroll
    for (int mi = 0; mi < 4; mi++)
#pragma unroll
        for (int r = 0; r < 2; r++) {
            float v = rs[mi][r];
            v += __shfl_xor_sync(0xffffffffu, v, 1);
            v += __shfl_xor_sync(0xffffffffu, v, 2);
            if (t == 0) atomicAdd(&g_Z[i0 + mi * 16 + r * 8 + g], v);
        }

    // col sums -> Z[j] (mirror blocks), skip on diagonal tiles
    if (ti != tj) {
#pragma unroll
        for (int ni = 0; ni < 4; ni++)
#pragma unroll
            for (int p = 0; p < 2; p++) {
                float v = cs[ni][p];
                v += __shfl_xor_sync(0xffffffffu, v, 4);
                v += __shfl_xor_sync(0xffffffffu, v, 8);
                v += __shfl_xor_sync(0xffffffffu, v, 16);
                if (l < 4) atomicAdd(&g_Z[j0 + ni * 8 + 2 * t + p], v);
            }
    }
}

// ---------------- K2b: vp[c][n] = bf16(x[c][n] / Z[n]) ----------------
__global__ void k2b_vprep(const float* __restrict__ x) {
    int wdx = blockIdx.x * 256 + threadIdx.x;
    int c  = wdx >> 12;
    int nw = wdx & 4095;
    int n  = nw * 2;
    float v0 = x[c * N_TOK + n]     / g_Z[n];
    float v1 = x[c * N_TOK + n + 1] / g_Z[n + 1];
    g_vp[wdx] = packbf(v0, v1);
}

// ---------------- KB: fused E-recompute + out GEMM (512 threads, 16 warps) ----------------
__global__ void __launch_bounds__(512, 1) kB_fused() {
    __shared__ __align__(16) unsigned sE[128 * 64];      // 32 KB  [m local][n words]
    __shared__ __align__(16) unsigned sVP[2][64 * 64];   // 32 KB  [c][n words] x2
    const int tid = threadIdx.x;
    const int l = tid & 31, w = tid >> 5;   // w 0..15
    const int g = l >> 2, t = l & 3;
    const int wm = w >> 2, wn = w & 3;      // phase1: 4(m) x 4(n)
    const int wc = w >> 3, wm2 = w & 7;     // phase2: 2(c) x 8(m)
    const int m0 = blockIdx.x * 128;

    const unsigned sEb  = (unsigned)__cvta_generic_to_shared(&sE[0]);
    const unsigned sVPb = (unsigned)__cvta_generic_to_shared(&sVP[0][0]);

    // preload A fragments (qT rows of this m-tile) — constant across iterations
    unsigned ap[2][2][4];
#pragma unroll
    for (int mi = 0; mi < 2; mi++)
#pragma unroll
        for (int kk = 0; kk < 2; kk++) {
            const unsigned* p = g_qT + (m0 + wm * 32 + mi * 16 + g) * 16 + kk * 8 + t;
            ap[mi][kk][0] = p[0];
            ap[mi][kk][1] = p[128];
            ap[mi][kk][2] = p[4];
            ap[mi][kk][3] = p[132];
        }

    float out[2][2][4];
#pragma unroll
    for (int ci = 0; ci < 2; ci++)
#pragma unroll
        for (int ni = 0; ni < 2; ni++)
            out[ci][ni][0] = out[ci][ni][1] = out[ci][ni][2] = out[ci][ni][3] = 0.0f;

    auto issueVP = [&](int buf, int nt) {
        // 64 rows x 16 chunks of 16B = 1024 chunks, 2 per thread
#pragma unroll
        for (int it = 0; it < 2; it++) {
            int idx = it * 512 + tid;
            int r = idx >> 4, c = idx & 15;
            cpasync16(sVPb + (buf * 4096 + r * 64 + ((c ^ (r & 7)) << 2)) * 4,
                      g_vp + r * 4096 + nt * 64 + c * 4);
        }
        asm volatile("cp.async.commit_group;" ::);
    };

    const int ntbase = blockIdx.y * 32;
    issueVP(0, ntbase);

    for (int it = 0; it < 32; it++) {
        const int nt = ntbase + it;
        const int n0 = nt * 128;
        if (it < 31) issueVP((it + 1) & 1, nt + 1);

        // ---- phase 1: S block -> ex2 -> sE ----
        unsigned b[4][2][2];
#pragma unroll
        for (int ni = 0; ni < 4; ni++)
#pragma unroll
            for (int kk = 0; kk < 2; kk++) {
                const unsigned* p = g_qT + (n0 + wn * 32 + ni * 8 + g) * 16 + kk * 8 + t;
                b[ni][kk][0] = p[0];
                b[ni][kk][1] = p[4];
            }
        float acc1[2][4][4];
#pragma unroll
        for (int mi = 0; mi < 2; mi++)
#pragma unroll
            for (int ni = 0; ni < 4; ni++) {
                acc1[mi][ni][0] = acc1[mi][ni][1] = acc1[mi][ni][2] = acc1[mi][ni][3] = 0.0f;
#pragma unroll
                for (int kk = 0; kk < 2; kk++) mma16816(acc1[mi][ni], ap[mi][kk], b[ni][kk]);
            }

#pragma unroll
        for (int mi = 0; mi < 2; mi++)
#pragma unroll
            for (int ni = 0; ni < 4; ni++) {
                float e0 = ex2f(acc1[mi][ni][0]);
                float e1 = ex2f(acc1[mi][ni][1]);
                float e2 = ex2f(acc1[mi][ni][2]);
                float e3 = ex2f(acc1[mi][ni][3]);
                int cw = wn * 16 + ni * 4 + t;
                int r0 = wm * 32 + mi * 16 + g;
                int r1 = r0 + 8;
                sE[r0 * 64 + swz(r0, cw)] = packbf(e0, e1);
                sE[r1 * 64 + swz(r1, cw)] = packbf(e2, e3);
            }

        __syncthreads();
        if (it < 31) { asm volatile("cp.async.wait_group 1;" ::); }
        else         { asm volatile("cp.async.wait_group 0;" ::); }

        // ---- phase 2: out += vp @ sE ----
        const unsigned vbuf = sVPb + (unsigned)((it & 1) * 4096 * 4);
#pragma unroll
        for (int kk = 0; kk < 8; kk++) {
            int chk = kk * 2 + (l >> 4);
            unsigned a2[2][4], b2[4];
#pragma unroll
            for (int ci = 0; ci < 2; ci++) {
                int r = wc * 32 + ci * 16 + (l & 15);
                ldsm4(a2[ci][0], a2[ci][1], a2[ci][2], a2[ci][3],
                      vbuf + (r * 64 + ((chk ^ (r & 7)) << 2)) * 4);
            }
            {
                int r = wm2 * 16 + (l & 15);
                ldsm4(b2[0], b2[1], b2[2], b2[3],
                      sEb + (r * 64 + ((chk ^ (r & 7)) << 2)) * 4);
            }
            unsigned bl[2] = {b2[0], b2[2]};
            unsigned bh[2] = {b2[1], b2[3]};
#pragma unroll
            for (int ci = 0; ci < 2; ci++) {
                mma16816(out[ci][0], a2[ci], bl);
                mma16816(out[ci][1], a2[ci], bh);
            }
        }
        __syncthreads();
    }

    // epilogue: partials
    float* P = g_P + blockIdx.y * (C_CH * N_TOK);
#pragma unroll
    for (int ci = 0; ci < 2; ci++)
#pragma unroll
        for (int ni = 0; ni < 2; ni++) {
            int c = wc * 32 + ci * 16 + g;
            int m = m0 + wm2 * 16 + ni * 8 + 2 * t;
            *(float2*)(P + c * N_TOK + m)       = make_float2(out[ci][ni][0], out[ci][ni][1]);
            *(float2*)(P + (c + 8) * N_TOK + m) = make_float2(out[ci][ni][2], out[ci][ni][3]);
        }
}

// ---------------- K4: out = x + sum_s P[s] ----------------
__global__ void k4_final(const float* __restrict__ x, float* __restrict__ out) {
    int idx = blockIdx.x * 256 + threadIdx.x;
    float s = x[idx];
#pragma unroll
    for (int sp = 0; sp < NSPLIT; sp++) s += g_P[sp * (C_CH * N_TOK) + idx];
    out[idx] = s;
}

extern "C" void kernel_launch(void* const* d_in, const int* in_sizes, int n_in,
                              void* d_out, int out_size) {
    const float* x    = (const float*)d_in[0];   // [64][8192]
    const float* W    = (const float*)d_in[1];   // [32][64]
    const float* bias = (const float*)d_in[2];   // [32]
    float* out = (float*)d_out;                  // [64][8192]

    k1_qproj<<<32, 256>>>(x, W, bias);
    kA_zsum<<<2080, 256>>>();
    k2b_vprep<<<1024, 256>>>(x);
    kB_fused<<<dim3(64, NSPLIT), 512>>>();
    k4_final<<<2048, 256>>>(x, out);
}

// round 5
// speedup vs baseline: 2.9893x; 1.1451x over previous
#include <cuda_runtime.h>
#include <cuda_bf16.h>
#include <cstdint>

#define N_TOK 8192
#define C_CH  64
#define CR_   32
#define NSPLIT 2

// Scratch
__device__ unsigned g_qT[N_TOK * 16];               // [8192][32] bf16, scaled by sqrt(log2e)*32^-0.25
__device__ float    g_Z[N_TOK];                     // row sums of exp(S)
__device__ unsigned g_vp[C_CH * 4096];              // [64][8192] bf16 = x / Z[n]
__device__ __align__(16) float g_P[NSPLIT * C_CH * N_TOK];  // split partials (4MB)

// ---------------- helpers ----------------
static __device__ __forceinline__ float ex2f(float x) {
    float r;
    asm("ex2.approx.f32 %0, %1;" : "=f"(r) : "f"(x));
    return r;
}

static __device__ __forceinline__ unsigned packbf(float lo, float hi) {
    unsigned u;
    asm("cvt.rn.bf16x2.f32 %0, %1, %2;" : "=r"(u) : "f"(hi), "f"(lo));
    return u;
}

static __device__ __forceinline__ void mma16816(float d[4], const unsigned a[4], const unsigned b[2]) {
    asm("mma.sync.aligned.m16n8k16.row.col.f32.bf16.bf16.f32 "
        "{%0,%1,%2,%3}, {%4,%5,%6,%7}, {%8,%9}, {%0,%1,%2,%3};"
        : "+f"(d[0]), "+f"(d[1]), "+f"(d[2]), "+f"(d[3])
        : "r"(a[0]), "r"(a[1]), "r"(a[2]), "r"(a[3]), "r"(b[0]), "r"(b[1]));
}

static __device__ __forceinline__ void ldsm4(unsigned& r0, unsigned& r1, unsigned& r2, unsigned& r3,
                                             unsigned saddr) {
    asm volatile("ldmatrix.sync.aligned.m8n8.x4.shared.b16 {%0,%1,%2,%3}, [%4];"
                 : "=r"(r0), "=r"(r1), "=r"(r2), "=r"(r3) : "r"(saddr));
}

static __device__ __forceinline__ void cpasync16(unsigned saddr, const void* gsrc) {
    asm volatile("cp.async.cg.shared.global [%0], [%1], 16;" :: "r"(saddr), "l"(gsrc));
}

static __device__ __forceinline__ int swz(int r, int w) {
    return (((w >> 2) ^ (r & 7)) << 2) | (w & 3);
}

// ---------------- K1: qT = (W@x + bias) * sqrt(log2e)*32^-0.25, zero Z ----------------
__global__ void k1_qproj(const float* __restrict__ x, const float* __restrict__ W,
                         const float* __restrict__ bias) {
    __shared__ float sW[CR_ * 64];
    __shared__ float sb[CR_];
    int tid = threadIdx.x;
    for (int i = tid; i < CR_ * 64; i += 256) sW[i] = W[i];
    if (tid < CR_) sb[tid] = bias[tid];
    __syncthreads();

    int n = blockIdx.x * 256 + tid;
    float q[CR_];
#pragma unroll
    for (int k = 0; k < CR_; k++) q[k] = sb[k];
#pragma unroll 4
    for (int c = 0; c < 64; c++) {
        float xv = x[c * N_TOK + n];
#pragma unroll
        for (int k = 0; k < CR_; k++) q[k] = fmaf(sW[k * 64 + c], xv, q[k]);
    }
    const float sc = 0.5050097687177836f;  // 32^-0.25 * sqrt(log2 e)
    unsigned* dst = g_qT + n * 16;
#pragma unroll
    for (int k = 0; k < 16; k++) dst[k] = packbf(q[2 * k] * sc, q[2 * k + 1] * sc);
    g_Z[n] = 0.0f;
}

// ---------------- KA: Z = rowsum(exp(S)), triangular launch (2080 CTAs) ----------------
__global__ void __launch_bounds__(256, 1) kA_zsum() {
    const int bid = blockIdx.x;
    int ti = (int)((129.0f - sqrtf(16641.0f - 8.0f * (float)bid)) * 0.5f);
    while (ti > 0 && bid < (129 * ti - ti * ti) / 2) ti--;
    while (bid >= (129 * (ti + 1) - (ti + 1) * (ti + 1)) / 2) ti++;
    const int tj = ti + (bid - (129 * ti - ti * ti) / 2);

    const int l = threadIdx.x & 31, w = threadIdx.x >> 5;
    const int g = l >> 2, t = l & 3;
    const int wm = w >> 2, wn = w & 3;
    const int i0 = ti * 128 + wm * 64;
    const int j0 = tj * 128 + wn * 32;

    unsigned a[4][2][4];
#pragma unroll
    for (int mi = 0; mi < 4; mi++)
#pragma unroll
        for (int kk = 0; kk < 2; kk++) {
            const unsigned* p = g_qT + (i0 + mi * 16 + g) * 16 + kk * 8 + t;
            a[mi][kk][0] = p[0];
            a[mi][kk][1] = p[128];
            a[mi][kk][2] = p[4];
            a[mi][kk][3] = p[132];
        }
    unsigned b[4][2][2];
#pragma unroll
    for (int ni = 0; ni < 4; ni++)
#pragma unroll
        for (int kk = 0; kk < 2; kk++) {
            const unsigned* p = g_qT + (j0 + ni * 8 + g) * 16 + kk * 8 + t;
            b[ni][kk][0] = p[0];
            b[ni][kk][1] = p[4];
        }

    float acc[4][4][4];
#pragma unroll
    for (int mi = 0; mi < 4; mi++)
#pragma unroll
        for (int ni = 0; ni < 4; ni++) {
            acc[mi][ni][0] = acc[mi][ni][1] = acc[mi][ni][2] = acc[mi][ni][3] = 0.0f;
#pragma unroll
            for (int kk = 0; kk < 2; kk++) mma16816(acc[mi][ni], a[mi][kk], b[ni][kk]);
        }

    float rs[4][2];
    float cs[4][2];
#pragma unroll
    for (int i = 0; i < 4; i++) { rs[i][0] = rs[i][1] = 0.0f; cs[i][0] = cs[i][1] = 0.0f; }

#pragma unroll
    for (int mi = 0; mi < 4; mi++)
#pragma unroll
        for (int ni = 0; ni < 4; ni++) {
            float e0 = ex2f(acc[mi][ni][0]);
            float e1 = ex2f(acc[mi][ni][1]);
            float e2 = ex2f(acc[mi][ni][2]);
            float e3 = ex2f(acc[mi][ni][3]);
            rs[mi][0] += e0 + e1;
            rs[mi][1] += e2 + e3;
            cs[ni][0] += e0 + e2;
            cs[ni][1] += e1 + e3;
        }

#pragma unroll
    for (int mi = 0; mi < 4; mi++)
#pragma unroll
        for (int r = 0; r < 2; r++) {
            float v = rs[mi][r];
            v += __shfl_xor_sync(0xffffffffu, v, 1);
            v += __shfl_xor_sync(0xffffffffu, v, 2);
            if (t == 0) atomicAdd(&g_Z[i0 + mi * 16 + r * 8 + g], v);
        }

    if (ti != tj) {
#pragma unroll
        for (int ni = 0; ni < 4; ni++)
#pragma unroll
            for (int p = 0; p < 2; p++) {
                float v = cs[ni][p];
                v += __shfl_xor_sync(0xffffffffu, v, 4);
                v += __shfl_xor_sync(0xffffffffu, v, 8);
                v += __shfl_xor_sync(0xffffffffu, v, 16);
                if (l < 4) atomicAdd(&g_Z[j0 + ni * 8 + 2 * t + p], v);
            }
    }
}

// ---------------- K2b: vp[c][n] = bf16(x[c][n] / Z[n]) ----------------
__global__ void k2b_vprep(const float* __restrict__ x) {
    int wdx = blockIdx.x * 256 + threadIdx.x;
    int c  = wdx >> 12;
    int nw = wdx & 4095;
    int n  = nw * 2;
    float v0 = x[c * N_TOK + n]     / g_Z[n];
    float v1 = x[c * N_TOK + n + 1] / g_Z[n + 1];
    g_vp[wdx] = packbf(v0, v1);
}

// ---------------- KB: fused E-recompute + out GEMM, software-pipelined ----------------
// 512 threads. Per body: ONE barrier; phase2(it) [tensor/LDSM] and phase1(it+1)
// [MUFU/STS] co-resident so warps overlap pipes. sE double-buffered; sVP/sQ
// triple-buffered with cp.async prefetch distance 2.
#define SMEM_KB_BYTES 139264
__global__ void __launch_bounds__(512, 1) kB_fused() {
    extern __shared__ __align__(16) unsigned smem[];
    // word offsets within dynamic smem
    const unsigned OFF_E  = 0;              // 2 * 128*64 = 16384 words (64 KB)
    const unsigned OFF_VP = 16384;          // 3 * 64*64  = 12288 words (48 KB)
    const unsigned OFF_Q  = 28672;          // 3 * 128*16 =  6144 words (24 KB)

    const int tid = threadIdx.x;
    const int l = tid & 31, w = tid >> 5;   // w 0..15
    const int g = l >> 2, t = l & 3;
    const int wm = w >> 2, wn = w & 3;      // phase1: 4(m) x 4(n)
    const int wc = w >> 3, wm2 = w & 7;     // phase2: 2(c) x 8(m)
    const int m0 = blockIdx.x * 128;

    const unsigned sb = (unsigned)__cvta_generic_to_shared(smem);

    // preload A fragments (qT rows of this m-tile) — constant across iterations
    unsigned ap[2][2][4];
#pragma unroll
    for (int mi = 0; mi < 2; mi++)
#pragma unroll
        for (int kk = 0; kk < 2; kk++) {
            const unsigned* p = g_qT + (m0 + wm * 32 + mi * 16 + g) * 16 + kk * 8 + t;
            ap[mi][kk][0] = p[0];
            ap[mi][kk][1] = p[128];
            ap[mi][kk][2] = p[4];
            ap[mi][kk][3] = p[132];
        }

    float out[2][2][4];
#pragma unroll
    for (int ci = 0; ci < 2; ci++)
#pragma unroll
        for (int ni = 0; ni < 2; ni++)
            out[ci][ni][0] = out[ci][ni][1] = out[ci][ni][2] = out[ci][ni][3] = 0.0f;

    const int ntbase = blockIdx.y * 32;

    // issue cp.async group for tile nt into rotation slot
    auto issue = [&](int slot, int nt) {
        // VP: 64 rows x 16 chunks of 16B
#pragma unroll
        for (int i2 = 0; i2 < 2; i2++) {
            int idx = i2 * 512 + tid;
            int r = idx >> 4, c = idx & 15;
            cpasync16(sb + (OFF_VP + slot * 4096 + r * 64 + ((c ^ (r & 7)) << 2)) * 4,
                      g_vp + r * 4096 + nt * 64 + c * 4);
        }
        // Q: 128 rows x 4 chunks of 16B (16-word pitch, chunk swizzle c^((r>>1)&3))
        {
            int r = tid >> 2, c = tid & 3;
            int cc = c ^ ((r >> 1) & 3);
            cpasync16(sb + (OFF_Q + slot * 2048 + r * 16 + cc * 4) * 4,
                      g_qT + (nt * 128 + r) * 16 + c * 4);
        }
        asm volatile("cp.async.commit_group;" ::);
    };

    // phase1: S(m-tile, n-tile) -> ex2 -> sE[ebuf]; B-frags from sQ[qslot]
    auto phase1 = [&](int qslot, int ebuf) {
        const unsigned qbase = sb + (OFF_Q + qslot * 2048) * 4;
#pragma unroll
        for (int gi = 0; gi < 2; gi++) {
            unsigned bfr[2][2][2];   // [h: n8 within 16][kk][2]
#pragma unroll
            for (int p = 0; p < 2; p++) {
                int r = wn * 32 + gi * 16 + (l & 15);
                int ch = (2 * p + (l >> 4)) ^ ((r >> 1) & 3);
                unsigned q0, q1, q2, q3;
                ldsm4(q0, q1, q2, q3, qbase + (r * 16 + ch * 4) * 4);
                bfr[0][p][0] = q0; bfr[0][p][1] = q2;   // rows 0-7: k0-7, k8-15
                bfr[1][p][0] = q1; bfr[1][p][1] = q3;   // rows 8-15
            }
#pragma unroll
            for (int mi = 0; mi < 2; mi++)
#pragma unroll
                for (int h = 0; h < 2; h++) {
                    float acc[4] = {0.0f, 0.0f, 0.0f, 0.0f};
                    mma16816(acc, ap[mi][0], bfr[h][0]);
                    mma16816(acc, ap[mi][1], bfr[h][1]);
                    float e0 = ex2f(acc[0]);
                    float e1 = ex2f(acc[1]);
                    float e2 = ex2f(acc[2]);
                    float e3 = ex2f(acc[3]);
                    int ni = gi * 2 + h;
                    int cw = wn * 16 + ni * 4 + t;
                    int r0 = wm * 32 + mi * 16 + g;
                    int r1 = r0 + 8;
                    smem[OFF_E + ebuf * 8192 + r0 * 64 + swz(r0, cw)] = packbf(e0, e1);
                    smem[OFF_E + ebuf * 8192 + r1 * 64 + swz(r1, cw)] = packbf(e2, e3);
                }
        }
    };

    // phase2: out += vp[vslot] @ sE[ebuf]
    auto phase2 = [&](int vslot, int ebuf) {
        const unsigned vbase = sb + (OFF_VP + vslot * 4096) * 4;
        const unsigned ebase = sb + (OFF_E + ebuf * 8192) * 4;
#pragma unroll
        for (int kk = 0; kk < 8; kk++) {
            int chk = kk * 2 + (l >> 4);
            unsigned a2[2][4], b2[4];
#pragma unroll
            for (int ci = 0; ci < 2; ci++) {
                int r = wc * 32 + ci * 16 + (l & 15);
                ldsm4(a2[ci][0], a2[ci][1], a2[ci][2], a2[ci][3],
                      vbase + (r * 64 + ((chk ^ (r & 7)) << 2)) * 4);
            }
            {
                int r = wm2 * 16 + (l & 15);
                ldsm4(b2[0], b2[1], b2[2], b2[3],
                      ebase + (r * 64 + ((chk ^ (r & 7)) << 2)) * 4);
            }
            unsigned bl[2] = {b2[0], b2[2]};
            unsigned bh[2] = {b2[1], b2[3]};
#pragma unroll
            for (int ci = 0; ci < 2; ci++) {
                mma16816(out[ci][0], a2[ci], bl);
                mma16816(out[ci][1], a2[ci], bh);
            }
        }
    };

    // prologue
    issue(0, ntbase);
    issue(1, ntbase + 1);
    asm volatile("cp.async.wait_group 1;" ::);
    __syncthreads();
    phase1(0, 0);                            // E(0) -> sE[0]

    // main loop: one barrier per body
    for (int it = 0; it < 32; it++) {
        asm volatile("cp.async.wait_group 0;" ::);
        __syncthreads();
        if (it <= 29) issue((it + 2) % 3, ntbase + it + 2);
        phase2(it % 3, it & 1);
        if (it < 31) phase1((it + 1) % 3, (it + 1) & 1);
    }

    // epilogue: partials
    float* P = g_P + blockIdx.y * (C_CH * N_TOK);
#pragma unroll
    for (int ci = 0; ci < 2; ci++)
#pragma unroll
        for (int ni = 0; ni < 2; ni++) {
            int c = wc * 32 + ci * 16 + g;
            int m = m0 + wm2 * 16 + ni * 8 + 2 * t;
            *(float2*)(P + c * N_TOK + m)       = make_float2(out[ci][ni][0], out[ci][ni][1]);
            *(float2*)(P + (c + 8) * N_TOK + m) = make_float2(out[ci][ni][2], out[ci][ni][3]);
        }
}

// ---------------- K4: out = x + sum_s P[s] ----------------
__global__ void k4_final(const float* __restrict__ x, float* __restrict__ out) {
    int idx = blockIdx.x * 256 + threadIdx.x;
    float s = x[idx];
#pragma unroll
    for (int sp = 0; sp < NSPLIT; sp++) s += g_P[sp * (C_CH * N_TOK) + idx];
    out[idx] = s;
}

extern "C" void kernel_launch(void* const* d_in, const int* in_sizes, int n_in,
                              void* d_out, int out_size) {
    const float* x    = (const float*)d_in[0];   // [64][8192]
    const float* W    = (const float*)d_in[1];   // [32][64]
    const float* bias = (const float*)d_in[2];   // [32]
    float* out = (float*)d_out;                  // [64][8192]

    cudaFuncSetAttribute(kB_fused, cudaFuncAttributeMaxDynamicSharedMemorySize, SMEM_KB_BYTES);

    k1_qproj<<<32, 256>>>(x, W, bias);
    kA_zsum<<<2080, 256>>>();
    k2b_vprep<<<1024, 256>>>(x);
    kB_fused<<<dim3(64, NSPLIT), 512, SMEM_KB_BYTES>>>();
    k4_final<<<2048, 256>>>(x, out);
}

// round 6
// speedup vs baseline: 3.1599x; 1.0571x over previous
#include <cuda_runtime.h>
#include <cuda_bf16.h>
#include <cstdint>

#define N_TOK 8192
#define C_CH  64
#define CR_   32
#define NSPLIT 2

// Scratch
__device__ unsigned g_qT[N_TOK * 16];               // [8192][32] bf16, scaled by sqrt(log2e)*32^-0.25
__device__ float    g_Z[N_TOK];                     // row sums of exp(S)
__device__ unsigned g_vp[C_CH * 4096];              // [64][8192] bf16 = x / Z[n]
__device__ __align__(16) float g_P[NSPLIT * C_CH * N_TOK];  // split partials (4MB)

// ---------------- helpers ----------------
static __device__ __forceinline__ float ex2f(float x) {
    float r;
    asm("ex2.approx.f32 %0, %1;" : "=f"(r) : "f"(x));
    return r;
}

static __device__ __forceinline__ unsigned packbf(float lo, float hi) {
    unsigned u;
    asm("cvt.rn.bf16x2.f32 %0, %1, %2;" : "=r"(u) : "f"(hi), "f"(lo));
    return u;
}

static __device__ __forceinline__ void mma16816(float d[4], const unsigned a[4], const unsigned b[2]) {
    asm("mma.sync.aligned.m16n8k16.row.col.f32.bf16.bf16.f32 "
        "{%0,%1,%2,%3}, {%4,%5,%6,%7}, {%8,%9}, {%0,%1,%2,%3};"
        : "+f"(d[0]), "+f"(d[1]), "+f"(d[2]), "+f"(d[3])
        : "r"(a[0]), "r"(a[1]), "r"(a[2]), "r"(a[3]), "r"(b[0]), "r"(b[1]));
}

static __device__ __forceinline__ void ldsm4(unsigned& r0, unsigned& r1, unsigned& r2, unsigned& r3,
                                             unsigned saddr) {
    asm volatile("ldmatrix.sync.aligned.m8n8.x4.shared.b16 {%0,%1,%2,%3}, [%4];"
                 : "=r"(r0), "=r"(r1), "=r"(r2), "=r"(r3) : "r"(saddr));
}

static __device__ __forceinline__ void cpasync16(unsigned saddr, const void* gsrc) {
    asm volatile("cp.async.cg.shared.global [%0], [%1], 16;" :: "r"(saddr), "l"(gsrc));
}

static __device__ __forceinline__ int swz(int r, int w) {
    return (((w >> 2) ^ (r & 7)) << 2) | (w & 3);
}

// ---------------- K1: qT = (W@x + bias) * sqrt(log2e)*32^-0.25, zero Z ----------------
__global__ void k1_qproj(const float* __restrict__ x, const float* __restrict__ W,
                         const float* __restrict__ bias) {
    __shared__ float sW[CR_ * 64];
    __shared__ float sb[CR_];
    int tid = threadIdx.x;
    for (int i = tid; i < CR_ * 64; i += 256) sW[i] = W[i];
    if (tid < CR_) sb[tid] = bias[tid];
    __syncthreads();

    int n = blockIdx.x * 256 + tid;
    float q[CR_];
#pragma unroll
    for (int k = 0; k < CR_; k++) q[k] = sb[k];
#pragma unroll 4
    for (int c = 0; c < 64; c++) {
        float xv = x[c * N_TOK + n];
#pragma unroll
        for (int k = 0; k < CR_; k++) q[k] = fmaf(sW[k * 64 + c], xv, q[k]);
    }
    const float sc = 0.5050097687177836f;  // 32^-0.25 * sqrt(log2 e)
    unsigned* dst = g_qT + n * 16;
#pragma unroll
    for (int k = 0; k < 16; k++) dst[k] = packbf(q[2 * k] * sc, q[2 * k + 1] * sc);
    g_Z[n] = 0.0f;
}

// ---------------- KA: Z = rowsum(exp(S)), triangular, smem-staged, streaming ----------------
__global__ void __launch_bounds__(256, 2) kA_zsum() {
    __shared__ __align__(16) unsigned sQ[2 * 128 * 16];   // 16 KB: [tile i | tile j]
    const int bid = blockIdx.x;
    int ti = (int)((129.0f - sqrtf(16641.0f - 8.0f * (float)bid)) * 0.5f);
    while (ti > 0 && bid < (129 * ti - ti * ti) / 2) ti--;
    while (bid >= (129 * (ti + 1) - (ti + 1) * (ti + 1)) / 2) ti++;
    const int tj = ti + (bid - (129 * ti - ti * ti) / 2);

    const int tid = threadIdx.x;
    const int l = tid & 31, w = tid >> 5;
    const int g = l >> 2, t = l & 3;
    const int wm = w >> 2, wn = w & 3;        // 2 x 4 warps; warp tile 64(i) x 32(j)
    const unsigned sqb = (unsigned)__cvta_generic_to_shared(sQ);

    // stage both q tiles: 1024 x 16B chunks
#pragma unroll
    for (int i2 = 0; i2 < 4; i2++) {
        int idx = i2 * 256 + tid;
        int tile = idx >> 9;
        int rr = (idx >> 2) & 127;
        int ch = idx & 3;
        int cc = ch ^ ((rr >> 1) & 3);
        int srow = (tile ? tj : ti) * 128 + rr;
        cpasync16(sqb + (tile * 2048 + rr * 16 + cc * 4) * 4, g_qT + srow * 16 + ch * 4);
    }
    asm volatile("cp.async.commit_group;" ::);
    asm volatile("cp.async.wait_group 0;" ::);
    __syncthreads();

    const unsigned qib = sqb;
    const unsigned qjb = sqb + 2048 * 4;

    float rs[4][2], cs[4][2];
#pragma unroll
    for (int i = 0; i < 4; i++) { rs[i][0] = rs[i][1] = 0.0f; cs[i][0] = cs[i][1] = 0.0f; }

#pragma unroll
    for (int mi = 0; mi < 4; mi++) {
        unsigned a0[4], a1[4];
        {
            int r = wm * 64 + mi * 16 + (l & 15);
            int c0 = ((l >> 4))     ^ ((r >> 1) & 3);
            int c1 = (2 + (l >> 4)) ^ ((r >> 1) & 3);
            ldsm4(a0[0], a0[1], a0[2], a0[3], qib + (r * 16 + c0 * 4) * 4);
            ldsm4(a1[0], a1[1], a1[2], a1[3], qib + (r * 16 + c1 * 4) * 4);
        }
#pragma unroll
        for (int nj = 0; nj < 2; nj++) {
            unsigned v0[4], v1[4];
            {
                int r = wn * 32 + nj * 16 + (l & 15);
                int c0 = ((l >> 4))     ^ ((r >> 1) & 3);
                int c1 = (2 + (l >> 4)) ^ ((r >> 1) & 3);
                ldsm4(v0[0], v0[1], v0[2], v0[3], qjb + (r * 16 + c0 * 4) * 4);
                ldsm4(v1[0], v1[1], v1[2], v1[3], qjb + (r * 16 + c1 * 4) * 4);
            }
#pragma unroll
            for (int h = 0; h < 2; h++) {
                float acc[4] = {0.0f, 0.0f, 0.0f, 0.0f};
                unsigned b0[2] = {v0[h], v0[h + 2]};
                unsigned b1[2] = {v1[h], v1[h + 2]};
                mma16816(acc, a0, b0);
                mma16816(acc, a1, b1);
                float e0 = ex2f(acc[0]);
                float e1 = ex2f(acc[1]);
                float e2 = ex2f(acc[2]);
                float e3 = ex2f(acc[3]);
                int ni = nj * 2 + h;
                rs[mi][0] += e0 + e1;
                rs[mi][1] += e2 + e3;
                cs[ni][0] += e0 + e2;
                cs[ni][1] += e1 + e3;
            }
        }
    }

    const int i0 = ti * 128 + wm * 64;
    const int j0 = tj * 128 + wn * 32;
#pragma unroll
    for (int mi = 0; mi < 4; mi++)
#pragma unroll
        for (int r = 0; r < 2; r++) {
            float v = rs[mi][r];
            v += __shfl_xor_sync(0xffffffffu, v, 1);
            v += __shfl_xor_sync(0xffffffffu, v, 2);
            if (t == 0) atomicAdd(&g_Z[i0 + mi * 16 + r * 8 + g], v);
        }
    if (ti != tj) {
#pragma unroll
        for (int ni = 0; ni < 4; ni++)
#pragma unroll
            for (int p = 0; p < 2; p++) {
                float v = cs[ni][p];
                v += __shfl_xor_sync(0xffffffffu, v, 4);
                v += __shfl_xor_sync(0xffffffffu, v, 8);
                v += __shfl_xor_sync(0xffffffffu, v, 16);
                if (l < 4) atomicAdd(&g_Z[j0 + ni * 8 + 2 * t + p], v);
            }
    }
}

// ---------------- K2b: vp[c][n] = bf16(x[c][n] / Z[n]) ----------------
__global__ void k2b_vprep(const float* __restrict__ x) {
    int wdx = blockIdx.x * 256 + threadIdx.x;
    int c  = wdx >> 12;
    int nw = wdx & 4095;
    int n  = nw * 2;
    float v0 = x[c * N_TOK + n]     / g_Z[n];
    float v1 = x[c * N_TOK + n + 1] / g_Z[n + 1];
    g_vp[wdx] = packbf(v0, v1);
}

// ---------------- KB: fused E-recompute + out GEMM ----------------
// phase2 operand swap: A = sE rows (m x k=n), B = vp rows (c x k=n) -> D[m][c].
// 16 warps = 4 m-groups x 4 n-split groups; sE read once, vp dup 4.
// n-split partials reduced via padded smem at the end.
#define SMEM_KB_BYTES 139264
__global__ void __launch_bounds__(512, 1) kB_fused() {
    extern __shared__ __align__(16) unsigned smem[];
    const unsigned OFF_E  = 0;              // 2 * 128*64 = 16384 words
    const unsigned OFF_VP = 16384;          // 3 * 64*64  = 12288 words
    const unsigned OFF_Q  = 28672;          // 3 * 128*16 =  6144 words

    const int tid = threadIdx.x;
    const int l = tid & 31, w = tid >> 5;   // w 0..15
    const int g = l >> 2, t = l & 3;
    const int wm = w >> 2, wn = w & 3;      // phase1: 4(m) x 4(n)
    const int wm2 = w & 3, nq = w >> 2;     // phase2: 4(m-groups) x 4(n-split)
    const int m0 = blockIdx.x * 128;

    const unsigned sb = (unsigned)__cvta_generic_to_shared(smem);

    // preload qT A-fragments for phase1 (constant per CTA)
    unsigned ap[2][2][4];
#pragma unroll
    for (int mi = 0; mi < 2; mi++)
#pragma unroll
        for (int kk = 0; kk < 2; kk++) {
            const unsigned* p = g_qT + (m0 + wm * 32 + mi * 16 + g) * 16 + kk * 8 + t;
            ap[mi][kk][0] = p[0];
            ap[mi][kk][1] = p[128];
            ap[mi][kk][2] = p[4];
            ap[mi][kk][3] = p[132];
        }

    float acc[2][8][4];   // [i: m16][j: c8][frag]
#pragma unroll
    for (int i = 0; i < 2; i++)
#pragma unroll
        for (int j = 0; j < 8; j++)
            acc[i][j][0] = acc[i][j][1] = acc[i][j][2] = acc[i][j][3] = 0.0f;

    const int ntbase = blockIdx.y * 32;

    auto issue = [&](int slot, int nt) {
#pragma unroll
        for (int i2 = 0; i2 < 2; i2++) {
            int idx = i2 * 512 + tid;
            int r = idx >> 4, c = idx & 15;
            cpasync16(sb + (OFF_VP + slot * 4096 + r * 64 + ((c ^ (r & 7)) << 2)) * 4,
                      g_vp + r * 4096 + nt * 64 + c * 4);
        }
        {
            int r = tid >> 2, c = tid & 3;
            int cc = c ^ ((r >> 1) & 3);
            cpasync16(sb + (OFF_Q + slot * 2048 + r * 16 + cc * 4) * 4,
                      g_qT + (nt * 128 + r) * 16 + c * 4);
        }
        asm volatile("cp.async.commit_group;" ::);
    };

    auto phase1 = [&](int qslot, int ebuf) {
        const unsigned qbase = sb + (OFF_Q + qslot * 2048) * 4;
#pragma unroll
        for (int gi = 0; gi < 2; gi++) {
            unsigned bfr[2][2][2];
#pragma unroll
            for (int p = 0; p < 2; p++) {
                int r = wn * 32 + gi * 16 + (l & 15);
                int ch = (2 * p + (l >> 4)) ^ ((r >> 1) & 3);
                unsigned q0, q1, q2, q3;
                ldsm4(q0, q1, q2, q3, qbase + (r * 16 + ch * 4) * 4);
                bfr[0][p][0] = q0; bfr[0][p][1] = q2;
                bfr[1][p][0] = q1; bfr[1][p][1] = q3;
            }
#pragma unroll
            for (int mi = 0; mi < 2; mi++)
#pragma unroll
                for (int h = 0; h < 2; h++) {
                    float a1[4] = {0.0f, 0.0f, 0.0f, 0.0f};
                    mma16816(a1, ap[mi][0], bfr[h][0]);
                    mma16816(a1, ap[mi][1], bfr[h][1]);
                    float e0 = ex2f(a1[0]);
                    float e1 = ex2f(a1[1]);
                    float e2 = ex2f(a1[2]);
                    float e3 = ex2f(a1[3]);
                    int ni = gi * 2 + h;
                    int cw = wn * 16 + ni * 4 + t;
                    int r0 = wm * 32 + mi * 16 + g;
                    int r1 = r0 + 8;
                    smem[OFF_E + ebuf * 8192 + r0 * 64 + swz(r0, cw)] = packbf(e0, e1);
                    smem[OFF_E + ebuf * 8192 + r1 * 64 + swz(r1, cw)] = packbf(e2, e3);
                }
        }
    };

    // phase2: acc[m][c] += sE(m, n-quarter) * vp(c, n-quarter)
    auto phase2 = [&](int vslot, int ebuf) {
        const unsigned vbase = sb + (OFF_VP + vslot * 4096) * 4;
        const unsigned ebase = sb + (OFF_E + ebuf * 8192) * 4;
#pragma unroll
        for (int kk = 0; kk < 2; kk++) {
            int ch = nq * 4 + kk * 2 + (l >> 4);
            unsigned a2[2][4], v2[4][4];
#pragma unroll
            for (int i = 0; i < 2; i++) {
                int r = wm2 * 32 + i * 16 + (l & 15);
                ldsm4(a2[i][0], a2[i][1], a2[i][2], a2[i][3],
                      ebase + (r * 64 + ((ch ^ (r & 7)) << 2)) * 4);
            }
#pragma unroll
            for (int cb = 0; cb < 4; cb++) {
                int r = cb * 16 + (l & 15);
                ldsm4(v2[cb][0], v2[cb][1], v2[cb][2], v2[cb][3],
                      vbase + (r * 64 + ((ch ^ (r & 7)) << 2)) * 4);
            }
#pragma unroll
            for (int i = 0; i < 2; i++)
#pragma unroll
                for (int cb = 0; cb < 4; cb++) {
                    unsigned bl[2] = {v2[cb][0], v2[cb][2]};
                    unsigned bh[2] = {v2[cb][1], v2[cb][3]};
                    mma16816(acc[i][cb * 2],     a2[i], bl);
                    mma16816(acc[i][cb * 2 + 1], a2[i], bh);
                }
        }
    };

    // prologue
    issue(0, ntbase);
    issue(1, ntbase + 1);
    asm volatile("cp.async.wait_group 1;" ::);
    __syncthreads();
    phase1(0, 0);

    for (int it = 0; it < 32; it++) {
        asm volatile("cp.async.wait_group 0;" ::);
        __syncthreads();
        if (it <= 29) issue((it + 2) % 3, ntbase + it + 2);
        phase2(it % 3, it & 1);
        if (it < 31) phase1((it + 1) % 3, (it + 1) & 1);
    }

    // epilogue: reduce 4 n-split partials via padded smem (stride 66), write g_P
    __syncthreads();
    float* sOut = (float*)smem;
    const int rbase = nq * 8448;   // 128*66 words per group
#pragma unroll
    for (int i = 0; i < 2; i++)
#pragma unroll
        for (int j = 0; j < 8; j++) {
            int m = wm2 * 32 + i * 16 + g;
            int c = j * 8 + 2 * t;
            sOut[rbase + m * 66 + c]           = acc[i][j][0];
            sOut[rbase + m * 66 + c + 1]       = acc[i][j][1];
            sOut[rbase + (m + 8) * 66 + c]     = acc[i][j][2];
            sOut[rbase + (m + 8) * 66 + c + 1] = acc[i][j][3];
        }
    __syncthreads();

    float* P = g_P + blockIdx.y * (C_CH * N_TOK);
    const int m = tid & 127;
    const int cb = tid >> 7;   // 0..3
#pragma unroll
    for (int cc = 0; cc < 16; cc++) {
        int c = cb * 16 + cc;
        float s = sOut[m * 66 + c] + sOut[8448 + m * 66 + c] +
                  sOut[16896 + m * 66 + c] + sOut[25344 + m * 66 + c];
        P[c * N_TOK + m0 + m] = s;
    }
}

// ---------------- K4: out = x + sum_s P[s] ----------------
__global__ void k4_final(const float* __restrict__ x, float* __restrict__ out) {
    int idx = blockIdx.x * 256 + threadIdx.x;
    float s = x[idx];
#pragma unroll
    for (int sp = 0; sp < NSPLIT; sp++) s += g_P[sp * (C_CH * N_TOK) + idx];
    out[idx] = s;
}

extern "C" void kernel_launch(void* const* d_in, const int* in_sizes, int n_in,
                              void* d_out, int out_size) {
    const float* x    = (const float*)d_in[0];   // [64][8192]
    const float* W    = (const float*)d_in[1];   // [32][64]
    const float* bias = (const float*)d_in[2];   // [32]
    float* out = (float*)d_out;                  // [64][8192]

    cudaFuncSetAttribute(kB_fused, cudaFuncAttributeMaxDynamicSharedMemorySize, SMEM_KB_BYTES);

    k1_qproj<<<32, 256>>>(x, W, bias);
    kA_zsum<<<2080, 256>>>();
    k2b_vprep<<<1024, 256>>>(x);
    kB_fused<<<dim3(64, NSPLIT), 512, SMEM_KB_BYTES>>>();
    k4_final<<<2048, 256>>>(x, out);
}